// round 13
// baseline (speedup 1.0000x reference)
#include <cuda_runtime.h>
#include <math.h>

#define CH 64
#define MAX_NODES 50000
#define NPB 64                    // nodes per GEMM tile
#define ASTR 65                   // A tile row stride (floats)
#define WSTR 128                  // W tile row stride (floats; mult of 4)
// A: 64k x 65 = 16640 B, W: 64k x 128 = 32768 B
#define GEMM_SMEM ((CH * ASTR + CH * WSTR) * (int)sizeof(float))   // 49408 B

// y = x @ phi^T  (written by GEMM, gathered by scatter; never needs zeroing)
__device__ float g_buf[MAX_NODES * CH];

// ---------------------------------------------------------------------------
// Kernel 1: dual GEMM.  For each node tile (64 nodes):
//   out[n][o]  = sum_k x[n][k] * psi[o][k]   (o = 0..63)
//   y[n][o]    = sum_k x[n][k] * phi[o][k]   (o = 0..63)
// One A staging serves both. Tile 64n x 128o x K=64. 256 threads,
// 4 blocks/SM (48 warps/SM). Per thread: 1 node x 32 outputs.
// Per k: 1 conflict-free scalar LDS (A) + 8 warp-uniform LDS.128 (W)
// + 32 FFMA (W processed in two 16-register chunks to bound reg pressure).
// ---------------------------------------------------------------------------
extern __shared__ float smem[];

__global__ void __launch_bounds__(256, 4) dual_gemm_kernel(
    const float* __restrict__ x,
    const float* __restrict__ phi,
    const float* __restrict__ psi,
    float* __restrict__ out,
    float* __restrict__ y,
    int N)
{
    float* As = smem;                 // As[k * 65 + n]
    float* Ws = smem + CH * ASTR;     // Ws[k * 128 + o]; o<64 = psi, o>=64 = phi
    int tid = threadIdx.x;
    int node0 = blockIdx.x * NPB;

    // Stage W: o fast across lanes -> STS banks = o%32 (conflict-free).
    // LDG per-lane strided 256B, but W is 32KB and reuse is L1-absorbed.
    for (int idx = tid; idx < WSTR * CH; idx += 256) {
        int o = idx & 127;
        int k = idx >> 7;
        float v = (o < CH) ? __ldg(&psi[o * CH + k])
                           : __ldg(&phi[(o - CH) * CH + k]);
        Ws[k * WSTR + o] = v;
    }

    // Stage A transposed: n fast across lanes -> STS banks = n%32 + const
    // (conflict-free). LDG: 16B per lane at 256B stride; pair-thread reuse
    // recovers sector halves via L1.
    for (int idx4 = tid; idx4 < NPB * 16; idx4 += 256) {
        int n  = idx4 & 63;
        int i4 = idx4 >> 6;
        int gn = node0 + n;
        float4 v = make_float4(0.f, 0.f, 0.f, 0.f);
        if (gn < N) {
            v = __ldg(reinterpret_cast<const float4*>(x + (size_t)gn * CH) + i4);
        }
        int k = i4 * 4;
        As[(k + 0) * ASTR + n] = v.x;
        As[(k + 1) * ASTR + n] = v.y;
        As[(k + 2) * ASTR + n] = v.z;
        As[(k + 3) * ASTR + n] = v.w;
    }
    __syncthreads();

    int nl = tid & 63;            // this thread's node within the tile
    int og = tid >> 6;            // 0..3: which 32-output group
    const float4* Wv = reinterpret_cast<const float4*>(Ws);
    int ow = og * 8;              // float4 offset of this thread's outputs

    float acc[32];
    #pragma unroll
    for (int o = 0; o < 32; o++) acc[o] = 0.f;

    #pragma unroll 2
    for (int k = 0; k < CH; k++) {
        float a = As[k * ASTR + nl];            // bank = (k+nl)%32: conflict-free
        const float4* wr = Wv + k * 32 + ow;    // warp-uniform -> broadcast
        // chunk 0: outputs 0..15
        {
            float4 w0 = wr[0], w1 = wr[1], w2 = wr[2], w3 = wr[3];
            acc[0]  += a * w0.x; acc[1]  += a * w0.y; acc[2]  += a * w0.z; acc[3]  += a * w0.w;
            acc[4]  += a * w1.x; acc[5]  += a * w1.y; acc[6]  += a * w1.z; acc[7]  += a * w1.w;
            acc[8]  += a * w2.x; acc[9]  += a * w2.y; acc[10] += a * w2.z; acc[11] += a * w2.w;
            acc[12] += a * w3.x; acc[13] += a * w3.y; acc[14] += a * w3.z; acc[15] += a * w3.w;
        }
        // chunk 1: outputs 16..31
        {
            float4 w4 = wr[4], w5 = wr[5], w6 = wr[6], w7 = wr[7];
            acc[16] += a * w4.x; acc[17] += a * w4.y; acc[18] += a * w4.z; acc[19] += a * w4.w;
            acc[20] += a * w5.x; acc[21] += a * w5.y; acc[22] += a * w5.z; acc[23] += a * w5.w;
            acc[24] += a * w6.x; acc[25] += a * w6.y; acc[26] += a * w6.z; acc[27] += a * w6.w;
            acc[28] += a * w7.x; acc[29] += a * w7.y; acc[30] += a * w7.z; acc[31] += a * w7.w;
        }
    }

    // Epilogue: og 0,1 -> out cols 0-31 / 32-63; og 2,3 -> y cols 0-31 / 32-63.
    int gn = node0 + nl;
    if (gn < N) {
        float* dst = ((og < 2) ? out : y) + (size_t)gn * CH + (og & 1) * 32;
        float4* d4 = reinterpret_cast<float4*>(dst);
        #pragma unroll
        for (int q = 0; q < 8; q++) {
            d4[q] = make_float4(acc[4 * q + 0], acc[4 * q + 1],
                                acc[4 * q + 2], acc[4 * q + 3]);
        }
    }
}

// ---------------------------------------------------------------------------
// Kernel 2: edge scatter.  out[dst] += ||edge_attr[e]|| * y[src]
// 16 threads per edge, one float4 per thread; leader loads metadata and
// probes the edge_index dtype inline (8 L1-cached words; int64 with values
// < 2^31 => those odd words are all zero — impossible for random int32).
// ---------------------------------------------------------------------------
__global__ void __launch_bounds__(256) edge_scatter_kernel(
    const float* __restrict__ y,
    const void* __restrict__ ei_raw,
    const float* __restrict__ ea,
    float* __restrict__ out,
    int E, int N)
{
    int t = blockIdx.x * blockDim.x + threadIdx.x;
    int e = t >> 4;
    if (e >= E) return;
    int lane = threadIdx.x & 15;
    int grpleader = threadIdx.x & 16;

    int src = 0, dst = 0;
    float scale = 0.f;
    if (lane == 0) {
        const int* e32 = (const int*)ei_raw;
        int hi = 0;
        #pragma unroll
        for (int j = 0; j < 8; j++) hi |= __ldg(&e32[2 * j + 1]);
        if (hi == 0) {   // int64
            const long long* ei = (const long long*)ei_raw;
            src = (int)__ldg(&ei[e]);
            dst = (int)__ldg(&ei[E + e]);
        } else {         // int32
            src = __ldg(&e32[e]);
            dst = __ldg(&e32[E + e]);
        }
        float a0 = __ldg(&ea[3 * e + 0]);
        float a1 = __ldg(&ea[3 * e + 1]);
        float a2 = __ldg(&ea[3 * e + 2]);
        scale = sqrtf(a0 * a0 + a1 * a1 + a2 * a2);
    }
    src   = __shfl_sync(0xffffffffu, src,   grpleader);
    dst   = __shfl_sync(0xffffffffu, dst,   grpleader);
    scale = __shfl_sync(0xffffffffu, scale, grpleader);

    if ((unsigned)src >= (unsigned)N || (unsigned)dst >= (unsigned)N) return;

    float4 v = __ldg(reinterpret_cast<const float4*>(y + (size_t)src * CH) + lane);
    v.x *= scale; v.y *= scale; v.z *= scale; v.w *= scale;

    float* addr = out + (size_t)dst * CH + lane * 4;
    asm volatile("red.global.add.v4.f32 [%0], {%1, %2, %3, %4};"
                 :: "l"(addr), "f"(v.x), "f"(v.y), "f"(v.z), "f"(v.w)
                 : "memory");
}

// ---------------------------------------------------------------------------
// Launch: GEMM (out = x@psi^T, y = x@phi^T), then scatter (out += scale*y[src]).
// ---------------------------------------------------------------------------
extern "C" void kernel_launch(void* const* d_in, const int* in_sizes, int n_in,
                              void* d_out, int out_size) {
    const float* x   = (const float*)d_in[0];
    const void*  ei  = d_in[1];
    const float* ea  = (const float*)d_in[2];
    const float* phi = (const float*)d_in[3];
    const float* psi = (const float*)d_in[4];
    float*       out = (float*)d_out;

    int N = in_sizes[0] / CH;   // 50000
    int E = in_sizes[1] / 2;    // 800000

    float* y = nullptr;
    cudaGetSymbolAddress((void**)&y, g_buf);

    // 1. dual GEMM
    cudaFuncSetAttribute(dual_gemm_kernel,
                         cudaFuncAttributeMaxDynamicSharedMemorySize, GEMM_SMEM);
    dual_gemm_kernel<<<(N + NPB - 1) / NPB, 256, GEMM_SMEM>>>(
        x, phi, psi, out, y, N);

    // 2. edge scatter into out
    long long tot = (long long)E * 16;
    int eblocks = (int)((tot + 255) / 256);
    edge_scatter_kernel<<<eblocks, 256>>>(y, ei, ea, out, E, N);
}

// round 14
// speedup vs baseline: 1.0516x; 1.0516x over previous
#include <cuda_runtime.h>
#include <math.h>

#define CH 64
#define MAX_NODES 50000
#define NPB 64                    // nodes per GEMM tile
#define ASTR 65                   // A tile row stride (floats)
#define WSTR 128                  // W tile row stride (floats; mult of 4)
#define GEMM_SMEM ((CH * ASTR + CH * WSTR) * (int)sizeof(float))   // 49408 B

// y = x @ phi^T  (written by GEMM, gathered by scatter; never needs zeroing)
__device__ float g_buf[MAX_NODES * CH];
// 1 if edge_index is int64, 0 if int32. Written by dual_gemm block 0 warp 0.
__device__ int g_is64;

// ---------------------------------------------------------------------------
// Kernel 1: dual GEMM.  For each node tile (64 nodes):
//   out[n][o] = sum_k x[n][k] * psi[o][k]
//   y[n][o]   = sum_k x[n][k] * phi[o][k]
// Tile 64n x 128o x K=64. 256 threads, 4 blocks/SM. 1 node x 32 outputs
// per thread. Block 0 warp 0 also probes the edge_index dtype (int64 with
// values < 2^31 => odd 32-bit words all zero; impossible for random int32).
// ---------------------------------------------------------------------------
extern __shared__ float smem[];

__global__ void __launch_bounds__(256, 4) dual_gemm_kernel(
    const float* __restrict__ x,
    const float* __restrict__ phi,
    const float* __restrict__ psi,
    const int* __restrict__ ei32,
    float* __restrict__ out,
    float* __restrict__ y,
    int N)
{
    float* As = smem;                 // As[k * 65 + n]
    float* Ws = smem + CH * ASTR;     // Ws[k * 128 + o]; o<64 = psi, o>=64 = phi
    int tid = threadIdx.x;
    int node0 = blockIdx.x * NPB;

    // dtype probe (block 0, warp 0) — off the scatter's critical path.
    if (blockIdx.x == 0 && tid < 32) {
        int nz = (__ldg(&ei32[2 * tid + 1]) != 0) ? 1 : 0;
        unsigned any = __ballot_sync(0xffffffffu, nz);
        if (tid == 0) g_is64 = (any == 0u) ? 1 : 0;
    }

    // Stage W: o fast across lanes -> conflict-free STS.
    for (int idx = tid; idx < WSTR * CH; idx += 256) {
        int o = idx & 127;
        int k = idx >> 7;
        float v = (o < CH) ? __ldg(&psi[o * CH + k])
                           : __ldg(&phi[(o - CH) * CH + k]);
        Ws[k * WSTR + o] = v;
    }

    // Stage A transposed: n fast across lanes -> conflict-free STS.
    for (int idx4 = tid; idx4 < NPB * 16; idx4 += 256) {
        int n  = idx4 & 63;
        int i4 = idx4 >> 6;
        int gn = node0 + n;
        float4 v = make_float4(0.f, 0.f, 0.f, 0.f);
        if (gn < N) {
            v = __ldg(reinterpret_cast<const float4*>(x + (size_t)gn * CH) + i4);
        }
        int k = i4 * 4;
        As[(k + 0) * ASTR + n] = v.x;
        As[(k + 1) * ASTR + n] = v.y;
        As[(k + 2) * ASTR + n] = v.z;
        As[(k + 3) * ASTR + n] = v.w;
    }
    __syncthreads();

    int nl = tid & 63;            // this thread's node within the tile
    int og = tid >> 6;            // 0..3: which 32-output group
    const float4* Wv = reinterpret_cast<const float4*>(Ws);
    int ow = og * 8;              // float4 offset of this thread's outputs

    float acc[32];
    #pragma unroll
    for (int o = 0; o < 32; o++) acc[o] = 0.f;

    #pragma unroll 2
    for (int k = 0; k < CH; k++) {
        float a = As[k * ASTR + nl];            // bank (k+nl)%32: conflict-free
        const float4* wr = Wv + k * 32 + ow;    // warp-uniform -> broadcast
        {
            float4 w0 = wr[0], w1 = wr[1], w2 = wr[2], w3 = wr[3];
            acc[0]  += a * w0.x; acc[1]  += a * w0.y; acc[2]  += a * w0.z; acc[3]  += a * w0.w;
            acc[4]  += a * w1.x; acc[5]  += a * w1.y; acc[6]  += a * w1.z; acc[7]  += a * w1.w;
            acc[8]  += a * w2.x; acc[9]  += a * w2.y; acc[10] += a * w2.z; acc[11] += a * w2.w;
            acc[12] += a * w3.x; acc[13] += a * w3.y; acc[14] += a * w3.z; acc[15] += a * w3.w;
        }
        {
            float4 w4 = wr[4], w5 = wr[5], w6 = wr[6], w7 = wr[7];
            acc[16] += a * w4.x; acc[17] += a * w4.y; acc[18] += a * w4.z; acc[19] += a * w4.w;
            acc[20] += a * w5.x; acc[21] += a * w5.y; acc[22] += a * w5.z; acc[23] += a * w5.w;
            acc[24] += a * w6.x; acc[25] += a * w6.y; acc[26] += a * w6.z; acc[27] += a * w6.w;
            acc[28] += a * w7.x; acc[29] += a * w7.y; acc[30] += a * w7.z; acc[31] += a * w7.w;
        }
    }

    // Epilogue: og 0,1 -> out cols 0-31 / 32-63; og 2,3 -> y cols 0-31 / 32-63.
    int gn = node0 + nl;
    if (gn < N) {
        float* dst = ((og < 2) ? out : y) + (size_t)gn * CH + (og & 1) * 32;
        float4* d4 = reinterpret_cast<float4*>(dst);
        #pragma unroll
        for (int q = 0; q < 8; q++) {
            d4[q] = make_float4(acc[4 * q + 0], acc[4 * q + 1],
                                acc[4 * q + 2], acc[4 * q + 3]);
        }
    }
}

// ---------------------------------------------------------------------------
// Kernel 2: edge scatter.  out[dst] += ||edge_attr[e]|| * y[src]
// 16 threads per edge, one float4 per thread; leader loads metadata.
// Dtype branch is a single uniform __ldg of g_is64 (probe done in GEMM).
// ---------------------------------------------------------------------------
__global__ void __launch_bounds__(256) edge_scatter_kernel(
    const float* __restrict__ y,
    const void* __restrict__ ei_raw,
    const float* __restrict__ ea,
    float* __restrict__ out,
    int E, int N)
{
    int t = blockIdx.x * blockDim.x + threadIdx.x;
    int e = t >> 4;
    if (e >= E) return;
    int lane = threadIdx.x & 15;
    int grpleader = threadIdx.x & 16;

    int src = 0, dst = 0;
    float scale = 0.f;
    if (lane == 0) {
        if (g_is64) {
            const long long* ei = (const long long*)ei_raw;
            src = (int)__ldg(&ei[e]);
            dst = (int)__ldg(&ei[E + e]);
        } else {
            const int* ei = (const int*)ei_raw;
            src = __ldg(&ei[e]);
            dst = __ldg(&ei[E + e]);
        }
        float a0 = __ldg(&ea[3 * e + 0]);
        float a1 = __ldg(&ea[3 * e + 1]);
        float a2 = __ldg(&ea[3 * e + 2]);
        scale = sqrtf(a0 * a0 + a1 * a1 + a2 * a2);
    }
    src   = __shfl_sync(0xffffffffu, src,   grpleader);
    dst   = __shfl_sync(0xffffffffu, dst,   grpleader);
    scale = __shfl_sync(0xffffffffu, scale, grpleader);

    if ((unsigned)src >= (unsigned)N || (unsigned)dst >= (unsigned)N) return;

    float4 v = __ldg(reinterpret_cast<const float4*>(y + (size_t)src * CH) + lane);
    v.x *= scale; v.y *= scale; v.z *= scale; v.w *= scale;

    float* addr = out + (size_t)dst * CH + lane * 4;
    asm volatile("red.global.add.v4.f32 [%0], {%1, %2, %3, %4};"
                 :: "l"(addr), "f"(v.x), "f"(v.y), "f"(v.z), "f"(v.w)
                 : "memory");
}

// ---------------------------------------------------------------------------
// Launch: GEMM (out = x@psi^T, y = x@phi^T, probe), then scatter.
// ---------------------------------------------------------------------------
extern "C" void kernel_launch(void* const* d_in, const int* in_sizes, int n_in,
                              void* d_out, int out_size) {
    const float* x   = (const float*)d_in[0];
    const void*  ei  = d_in[1];
    const float* ea  = (const float*)d_in[2];
    const float* phi = (const float*)d_in[3];
    const float* psi = (const float*)d_in[4];
    float*       out = (float*)d_out;

    int N = in_sizes[0] / CH;   // 50000
    int E = in_sizes[1] / 2;    // 800000

    float* y = nullptr;
    cudaGetSymbolAddress((void**)&y, g_buf);

    // 1. dual GEMM (+ dtype probe in block 0)
    cudaFuncSetAttribute(dual_gemm_kernel,
                         cudaFuncAttributeMaxDynamicSharedMemorySize, GEMM_SMEM);
    dual_gemm_kernel<<<(N + NPB - 1) / NPB, 256, GEMM_SMEM>>>(
        x, phi, psi, (const int*)ei, out, y, N);

    // 2. edge scatter into out
    long long tot = (long long)E * 16;
    int eblocks = (int)((tot + 255) / 256);
    edge_scatter_kernel<<<eblocks, 256>>>(y, ei, ea, out, E, N);
}